// round 9
// baseline (speedup 1.0000x reference)
#include <cuda_runtime.h>
#include <cuda_bf16.h>
#include <math_constants.h>
#include <cstdint>

// Problem constants
#define BB 8
#define NN 1024
#define TT 64
#define ELEMS (BB*NN*TT)  // 524288

// Scratch (no allocations allowed)
__device__ __nv_bfloat16 g_Ah[1024 * 1024];  // A[m=j][k=i] = adj[i][j], hi part
__device__ __nv_bfloat16 g_Al[1024 * 1024];  // lo part
__device__ __nv_bfloat16 g_Bh[1024 * 1024];  // B[n=c][k=i] = X[i][c], hi part
__device__ __nv_bfloat16 g_Bl[1024 * 1024];  // lo part (x1 half only; mask half exact)
__device__ float g_U[1024 * 1024];           // U[j*1024 + c]
__device__ float g_S[1024];                  // column sums of adj (atomic-accumulated)
// Epilogue coefficient tables
__device__ float g_scd[512];         // [h][8] = r1,r1,r2,r2,r3,r3,r4,r4
__device__ float g_c12[256];         // [h][4] = c1,c1,c2,c2
__device__ float g_r56[128];         // [h][2] = r5,r6
__device__ float g_mt[65];           // sorted MLP breakpoints (1-based)
__device__ float g_msa[65];          // piecewise slope table
__device__ float g_msb[65];          // piecewise intercept table

// ---------- helpers ----------
union U64 { unsigned long long u; float2 f; };

__device__ __forceinline__ unsigned long long ffma2(unsigned long long a,
                                                    unsigned long long b,
                                                    unsigned long long c) {
    unsigned long long d;
    asm("fma.rn.f32x2 %0, %1, %2, %3;" : "=l"(d) : "l"(a), "l"(b), "l"(c));
    return d;
}
__device__ __forceinline__ unsigned long long pack2(float x, float y) {
    U64 u; u.f = make_float2(x, y); return u.u;
}
__device__ __forceinline__ uint32_t smem_u32(const void* p) {
    uint32_t a;
    asm("{ .reg .u64 t; cvta.to.shared.u64 t, %1; cvt.u32.u64 %0, t; }" : "=r"(a) : "l"(p));
    return a;
}
__device__ __forceinline__ void cpasync16(uint32_t s, const void* g) {
    asm volatile("cp.async.cg.shared.global [%0], [%1], 16;" :: "r"(s), "l"(g));
}
#define CP_COMMIT() asm volatile("cp.async.commit_group;" ::: "memory")

__device__ __forceinline__ void ldm_x4(uint32_t& r0, uint32_t& r1, uint32_t& r2,
                                       uint32_t& r3, uint32_t a) {
    asm volatile("ldmatrix.sync.aligned.m8n8.x4.shared.b16 {%0,%1,%2,%3}, [%4];"
                 : "=r"(r0), "=r"(r1), "=r"(r2), "=r"(r3) : "r"(a));
}
__device__ __forceinline__ void mma_bf16(float& c0, float& c1, float& c2, float& c3,
                                         uint32_t a0, uint32_t a1, uint32_t a2, uint32_t a3,
                                         uint32_t b0, uint32_t b1) {
    asm volatile(
        "mma.sync.aligned.m16n8k16.row.col.f32.bf16.bf16.f32 "
        "{%0,%1,%2,%3}, {%4,%5,%6,%7}, {%8,%9}, {%0,%1,%2,%3};"
        : "+f"(c0), "+f"(c1), "+f"(c2), "+f"(c3)
        : "r"(a0), "r"(a1), "r"(a2), "r"(a3), "r"(b0), "r"(b1));
}

// ---------------------------------------------------------------------------
// Kernel 1: fold all linear layers (h == 0 collapse) + build epilogue tables
// Also zeroes g_S for the fused colsum atomics (stream-ordered before prep).
// ---------------------------------------------------------------------------
__global__ void coef_kernel(const float* __restrict__ Win, const float* __restrict__ bin,
                            const float* __restrict__ Wgc, const float* __restrict__ bgc,
                            const float* __restrict__ Wlo, const float* __restrict__ blo,
                            const float* __restrict__ Wro, const float* __restrict__ prelu_a,
                            const float* __restrict__ Wo1, const float* __restrict__ bo1,
                            const float* __restrict__ Wo2, const float* __restrict__ bo2,
                            const float* __restrict__ bro) {
    __shared__ float sA[64], sC[64], sB[64];
    __shared__ float G[6][64];
    __shared__ float st[64], scz[64];
    __shared__ float srt_t[64], srt_a[64], srt_b[64];
    __shared__ int   srt_p[64];
    int t = threadIdx.x;  // 0..63
    for (int i = t; i < 1024; i += 64) g_S[i] = 0.f;
    sA[t] = Win[t * 66 + 0];
    sC[t] = Win[t * 66 + 1];
    sB[t] = bin[t];
    __syncthreads();
    float g1 = 0, g2 = 0, g3 = 0, g4 = 0, g5 = 0, g6 = 0;
    for (int h = 0; h < 64; h++) {
        float w0 = Wgc[t * 128 + h];
        float w1 = Wgc[t * 128 + 64 + h];
        g1 = fmaf(w0, sA[h], g1);
        g2 = fmaf(w0, sC[h], g2);
        g3 = fmaf(w0, sB[h], g3);
        g4 = fmaf(w1, sA[h], g4);
        g5 = fmaf(w1, sC[h], g5);
        g6 = fmaf(w1, sB[h], g6);
    }
    G[0][t] = g1; G[1][t] = g2; G[2][t] = g4;
    G[3][t] = g5; G[4][t] = g6; G[5][t] = g3 + bgc[t];
    __syncthreads();
    float r[6] = {0, 0, 0, 0, 0, 0};
    for (int o = 0; o < 64; o++) {
        float w = Wlo[t * 128 + o];
        r[0] = fmaf(w, G[0][o], r[0]);
        r[1] = fmaf(w, G[1][o], r[1]);
        r[2] = fmaf(w, G[2][o], r[2]);
        r[3] = fmaf(w, G[3][o], r[3]);
        r[4] = fmaf(w, G[4][o], r[4]);
        r[5] = fmaf(w, G[5][o], r[5]);
    }
    r[5] += blo[t];
    g_scd[t * 8 + 0] = r[0]; g_scd[t * 8 + 1] = r[0];
    g_scd[t * 8 + 2] = r[1]; g_scd[t * 8 + 3] = r[1];
    g_scd[t * 8 + 4] = r[2]; g_scd[t * 8 + 5] = r[2];
    g_scd[t * 8 + 6] = r[3]; g_scd[t * 8 + 7] = r[3];
    g_r56[t * 2 + 0] = r[4]; g_r56[t * 2 + 1] = r[5];
    float wr = Wro[t];
    float wp = wr;
    float wn = wr * prelu_a[0];
    float c1 = 0.5f * (wp + wn);
    float c2 = 0.5f * (wp - wn);
    g_c12[t * 4 + 0] = c1; g_c12[t * 4 + 1] = c1;
    g_c12[t * 4 + 2] = c2; g_c12[t * 4 + 3] = c2;

    // piecewise-linear MLP tables
    float s1 = Wo1[t];
    float s2p = fmaf(s1, bro[0], bo1[t]);
    float s3 = Wo2[t];
    float tf, af, bf, cz = 0.f;
    int isP;
    if (s1 > 0.f)      { tf = -s2p / s1; isP = 1; af = s3 * s1; bf = s3 * s2p; }
    else if (s1 < 0.f) { tf = -s2p / s1; isP = 0; af = s3 * s1; bf = s3 * s2p; }
    else               { tf = CUDART_INF_F; isP = 0; af = 0.f; bf = 0.f;
                         cz = s3 * fmaxf(s2p, 0.f); }
    st[t] = tf; scz[t] = cz;
    __syncthreads();
    int rank = 0;
    for (int g = 0; g < 64; g++) {
        float tg = st[g];
        if (tg < tf || (tg == tf && g < t)) rank++;
    }
    srt_t[rank] = tf; srt_a[rank] = af; srt_b[rank] = bf; srt_p[rank] = isP;
    __syncthreads();
    float C0 = bo2[0];
    for (int g = 0; g < 64; g++) C0 += scz[g];
    for (int k = t; k <= 64; k += 64) {
        float A = 0.f, Bv = 0.f;
        for (int i = 0; i < 64; i++) {
            bool act = srt_p[i] ? (i < k) : (i >= k);
            if (act) { A += srt_a[i]; Bv += srt_b[i]; }
        }
        g_msa[k] = A;
        g_msb[k] = Bv + C0;
    }
    if (t < 64) g_mt[t + 1] = srt_t[t];
    if (t == 0) g_mt[0] = -CUDART_INF_F;
}

// ---------------------------------------------------------------------------
// Kernel 2 (fused prep): blocks 0..1023 convert adj -> Ah/Al (+colsum atomics);
// blocks 1024..1279 convert x/mask -> Bh/Bl. Independent work, one launch.
// ---------------------------------------------------------------------------
__global__ __launch_bounds__(256) void prep_kernel(const float* __restrict__ adj,
                                                   const float* __restrict__ x,
                                                   const int* __restrict__ mask,
                                                   const float* __restrict__ bfs) {
    int tid = threadIdx.x;
    if (blockIdx.x < 1024) {
        // ---- convertA part ----
        __shared__ float tile[32][33];
        int tx = tid & 31, ty = tid >> 5;  // 32 x 8
        int j0 = (blockIdx.x & 31) * 32, i0 = (blockIdx.x >> 5) * 32;
        #pragma unroll
        for (int s = 0; s < 4; s++)
            tile[ty + 8 * s][tx] = adj[(i0 + ty + 8 * s) * 1024 + j0 + tx];
        __syncthreads();
        #pragma unroll
        for (int s = 0; s < 4; s++) {
            float v = tile[tx][ty + 8 * s];
            __nv_bfloat16 h = __float2bfloat16_rn(v);
            __nv_bfloat16 l = __float2bfloat16_rn(v - __bfloat162float(h));
            int idx = (j0 + ty + 8 * s) * 1024 + i0 + tx;
            g_Ah[idx] = h;
            g_Al[idx] = l;
        }
        if (ty == 0) {
            float s = 0.f;
            #pragma unroll
            for (int r = 0; r < 32; r++) s += tile[r][tx];
            atomicAdd(&g_S[j0 + tx], s);
        }
    } else {
        // ---- convertX part ----
        __shared__ float sx[32][65];
        __shared__ float sm[32][65];
        int idx = blockIdx.x - 1024;       // 0..255
        int b = idx >> 5, i0 = (idx & 31) * 32;
        int r = tid >> 3;
        int c8 = (tid & 7) * 8;
        int base = (b * 1024 + i0 + r) * 64 + c8;
        {
            float4 v0 = *(const float4*)&x[base];
            float4 v1 = *(const float4*)&x[base + 4];
            int4 m0v = *(const int4*)&mask[base];
            int4 m1v = *(const int4*)&mask[base + 4];
            sx[r][c8 + 0] = v0.x; sx[r][c8 + 1] = v0.y; sx[r][c8 + 2] = v0.z; sx[r][c8 + 3] = v0.w;
            sx[r][c8 + 4] = v1.x; sx[r][c8 + 5] = v1.y; sx[r][c8 + 6] = v1.z; sx[r][c8 + 7] = v1.w;
            sm[r][c8 + 0] = (float)m0v.x; sm[r][c8 + 1] = (float)m0v.y;
            sm[r][c8 + 2] = (float)m0v.z; sm[r][c8 + 3] = (float)m0v.w;
            sm[r][c8 + 4] = (float)m1v.x; sm[r][c8 + 5] = (float)m1v.y;
            sm[r][c8 + 6] = (float)m1v.z; sm[r][c8 + 7] = (float)m1v.w;
        }
        __syncthreads();
        float bfs0 = bfs[0];
        int t = tid >> 2;
        int iq = (tid & 3) * 8;
        __align__(16) __nv_bfloat16 hh[8], ll[8], mh[8];
        #pragma unroll
        for (int q = 0; q < 8; q++) {
            float mv = sm[iq + q][t];
            float xv = sx[iq + q][t];
            float x1 = (mv != 0.0f) ? xv : bfs0;
            __nv_bfloat16 h = __float2bfloat16_rn(x1);
            hh[q] = h;
            ll[q] = __float2bfloat16_rn(x1 - __bfloat162float(h));
            mh[q] = __float2bfloat16_rn(mv);
        }
        int c1 = b * 64 + t;
        int row1 = c1 * 1024 + i0 + iq;
        *(uint4*)&g_Bh[row1] = *(uint4*)&hh[0];
        *(uint4*)&g_Bl[row1] = *(uint4*)&ll[0];
        int row2 = (512 + c1) * 1024 + i0 + iq;
        *(uint4*)&g_Bh[row2] = *(uint4*)&mh[0];
    }
}

// ---------------------------------------------------------------------------
// Kernel 3: bf16 tensor-core GEMM, fused 3-term accumulation per k-chunk.
// 512 threads / 16 warps (4m x 4n layout), 3-stage cp.async pipeline,
// x4-ldmatrix, ks-level frag pipelining. CTA tile M=64 x N=128 paired.
// ---------------------------------------------------------------------------
#define ROWB 144
#define AH_OFF 0
#define AL_OFF (64 * ROWB)         // 9216
#define BH_OFF (128 * ROWB)        // 18432
#define BL_OFF (256 * ROWB)        // 36864
#define BUFB   (320 * ROWB)        // 46080
#define MMA_SMEM (3 * BUFB)        // 138240

struct Frags {
    uint32_t ah[4], al[4];
    uint32_t bh0[4], bh1[4], bl0[2], bl1[2];
};

__device__ __forceinline__ void load_frags(Frags& f, uint32_t sb, int ks,
                                           uint32_t a_rel, uint32_t bh_b0,
                                           uint32_t bh_b1, uint32_t bl_b) {
    uint32_t o = ks * 32;
    ldm_x4(f.bh0[0], f.bh1[0], f.bh0[1], f.bh1[1], sb + bh_b0 + o);
    ldm_x4(f.bh0[2], f.bh1[2], f.bh0[3], f.bh1[3], sb + bh_b1 + o);
    ldm_x4(f.bl0[0], f.bl1[0], f.bl0[1], f.bl1[1], sb + bl_b + o);
    ldm_x4(f.ah[0], f.ah[1], f.ah[2], f.ah[3], sb + AH_OFF + a_rel + o);
    ldm_x4(f.al[0], f.al[1], f.al[2], f.al[3], sb + AL_OFF + a_rel + o);
}

__global__ __launch_bounds__(512) void mma_kernel() {
    extern __shared__ __align__(16) char smem[];
    int tid = threadIdx.x;
    int wid = tid >> 5, lane = tid & 31;
    int m0 = (blockIdx.x >> 3) * 64;
    int pn64 = (blockIdx.x & 7) * 64;
    uint32_t sbase = smem_u32(smem);

    // cp.async mapping: 5 chunks of 16B per thread per iteration (320 rows x 8)
    uint32_t soff[5];
    const __nv_bfloat16* gp[5];
    #pragma unroll
    for (int q = 0; q < 5; q++) {
        int c = tid + 512 * q;          // 0..2559
        int row = c >> 3, col = c & 7;
        soff[q] = row * ROWB + col * 16;
        if (row < 64) {
            gp[q] = g_Ah + (m0 + row) * 1024 + col * 8;
        } else if (row < 128) {
            gp[q] = g_Al + (m0 + row - 64) * 1024 + col * 8;
        } else if (row < 256) {
            int r = row - 128;
            int gcol = (r < 64) ? (pn64 + r) : (512 + pn64 + r - 64);
            gp[q] = g_Bh + gcol * 1024 + col * 8;
        } else {
            gp[q] = g_Bl + (pn64 + row - 256) * 1024 + col * 8;
        }
    }

    float acc[4][4];
    #pragma unroll
    for (int nt = 0; nt < 4; nt++)
        #pragma unroll
        for (int q = 0; q < 4; q++) acc[nt][q] = 0.f;

    int warp_m = (wid >> 2) * 16;        // 4 m-groups of 16 rows
    int w2 = wid & 3;                    // 16-col slice within each half
    uint32_t a_rel = (warp_m + (lane & 15)) * ROWB + ((lane >> 4) & 1) * 16;
    uint32_t x4row = (lane & 7) + ((lane >> 4) & 1) * 8;
    uint32_t x4chk = ((lane >> 3) & 1) * 16;
    uint32_t bh_b0 = BH_OFF + (w2 * 16 + x4row) * ROWB + x4chk;
    uint32_t bh_b1 = BH_OFF + (64 + w2 * 16 + x4row) * ROWB + x4chk;
    uint32_t bl_b  = BL_OFF + (w2 * 16 + x4row) * ROWB + x4chk;

    // prologue: stage 0 and 1
    #pragma unroll
    for (int q = 0; q < 5; q++) cpasync16(sbase + soff[q], gp[q]);
    CP_COMMIT();
    #pragma unroll
    for (int q = 0; q < 5; q++) cpasync16(sbase + BUFB + soff[q], gp[q] + 64);
    CP_COMMIT();

    for (int it = 0; it < 16; it++) {
        int buf = it % 3;
        if (it + 2 < 16) {
            int k0 = (it + 2) * 64;
            uint32_t sb = sbase + ((it + 2) % 3) * BUFB;
            #pragma unroll
            for (int q = 0; q < 5; q++) cpasync16(sb + soff[q], gp[q] + k0);
            CP_COMMIT();
            asm volatile("cp.async.wait_group 2;" ::: "memory");
        } else if (it == 14) {
            asm volatile("cp.async.wait_group 1;" ::: "memory");
        } else {
            asm volatile("cp.async.wait_group 0;" ::: "memory");
        }
        __syncthreads();

        uint32_t sb = sbase + buf * BUFB;
        Frags F;
        load_frags(F, sb, 0, a_rel, bh_b0, bh_b1, bl_b);
        #pragma unroll
        for (int ks = 0; ks < 4; ks++) {
            Frags Fn;
            if (ks < 3) load_frags(Fn, sb, ks + 1, a_rel, bh_b0, bh_b1, bl_b);
            // p0: Ah * Bh (all 4 n-tiles)
            #pragma unroll
            for (int nt = 0; nt < 4; nt++)
                mma_bf16(acc[nt][0], acc[nt][1], acc[nt][2], acc[nt][3],
                         F.ah[0], F.ah[1], F.ah[2], F.ah[3], F.bh0[nt], F.bh1[nt]);
            // p1: Ah * Bl (x1 n-tiles only)
            #pragma unroll
            for (int nt = 0; nt < 2; nt++)
                mma_bf16(acc[nt][0], acc[nt][1], acc[nt][2], acc[nt][3],
                         F.ah[0], F.ah[1], F.ah[2], F.ah[3], F.bl0[nt], F.bl1[nt]);
            // p2: Al * Bh (all 4 n-tiles)
            #pragma unroll
            for (int nt = 0; nt < 4; nt++)
                mma_bf16(acc[nt][0], acc[nt][1], acc[nt][2], acc[nt][3],
                         F.al[0], F.al[1], F.al[2], F.al[3], F.bh0[nt], F.bh1[nt]);
            if (ks < 3) F = Fn;
        }
        __syncthreads();
    }

    int r0 = m0 + warp_m + (lane >> 2);
    #pragma unroll
    for (int nt = 0; nt < 4; nt++) {
        int cb = (nt >= 2 ? 512 : 0) + pn64 + w2 * 16 + (nt & 1) * 8 + (lane & 3) * 2;
        *(float2*)&g_U[(size_t)r0 * 1024 + cb] = make_float2(acc[nt][0], acc[nt][1]);
        *(float2*)&g_U[(size_t)(r0 + 8) * 1024 + cb] = make_float2(acc[nt][2], acc[nt][3]);
    }
}

// ---------------------------------------------------------------------------
// Kernel 4: pointwise epilogue (f32x2 head + piecewise-linear MLP)
// ---------------------------------------------------------------------------
__global__ __launch_bounds__(256) void epilogue_kernel(
    const float* __restrict__ x, const int* __restrict__ mask,
    const float* __restrict__ bfs, float* __restrict__ out) {
    __shared__ float s_scd[512];
    __shared__ float s_c12[256];
    __shared__ float s_r56[128];
    __shared__ float s_mt[65], s_msa[65], s_msb[65];
    int tid = threadIdx.x;
    for (int i = tid; i < 512; i += 256) s_scd[i] = g_scd[i];
    s_c12[tid] = g_c12[tid];
    if (tid < 128) s_r56[tid] = g_r56[tid];
    if (tid < 65) { s_mt[tid] = g_mt[tid]; s_msa[tid] = g_msa[tid]; s_msb[tid] = g_msb[tid]; }
    __syncthreads();
    float bfs0 = bfs[0];

    int gid = blockIdx.x * 256 + tid;
    int e = gid * 4;
    int b = e >> 16;
    int rem = e & 65535;
    int j = rem >> 6;
    int tt = rem & 63;
    int c = b * 64 + tt;

    float4 xv = *(const float4*)&x[e];
    int4 mv = *(const int4*)&mask[e];
    size_t ubase = (size_t)j * 1024 + c;
    float4 u1v = *(const float4*)&g_U[ubase];
    float4 u2v = *(const float4*)&g_U[ubase + 512];
    float sj = g_S[j];

    float x1a[4], mfa[4];
    x1a[0] = mv.x ? xv.x : bfs0; mfa[0] = (float)mv.x;
    x1a[1] = mv.y ? xv.y : bfs0; mfa[1] = (float)mv.y;
    x1a[2] = mv.z ? xv.z : bfs0; mfa[2] = (float)mv.z;
    x1a[3] = mv.w ? xv.w : bfs0; mfa[3] = (float)mv.w;

    unsigned long long x1p[2] = { pack2(x1a[0], x1a[1]), pack2(x1a[2], x1a[3]) };
    unsigned long long mfp[2] = { pack2(mfa[0], mfa[1]), pack2(mfa[2], mfa[3]) };
    unsigned long long u1p[2] = { pack2(u1v.x, u1v.y), pack2(u1v.z, u1v.w) };
    unsigned long long u2p[2] = { pack2(u2v.x, u2v.y), pack2(u2v.z, u2v.w) };

    unsigned long long acc2[2] = { 0ULL, 0ULL };
    #pragma unroll 4
    for (int h = 0; h < 64; h++) {
        ulonglong2 r12 = *(const ulonglong2*)&s_scd[h * 8];
        ulonglong2 r34 = *(const ulonglong2*)&s_scd[h * 8 + 4];
        float2 r56v = *(const float2*)&s_r56[h * 2];
        ulonglong2 cc = *(const ulonglong2*)&s_c12[h * 4];
        float base = fmaf(r56v.x, sj, r56v.y);
        unsigned long long base2 = pack2(base, base);
        #pragma unroll
        for (int q = 0; q < 2; q++) {
            unsigned long long v =
                ffma2(r12.x, x1p[q],
                ffma2(r12.y, mfp[q],
                ffma2(r34.x, u1p[q],
                ffma2(r34.y, u2p[q], base2))));
            unsigned long long av = v & 0x7fffffff7fffffffULL;
            acc2[q] = ffma2(cc.x, v, acc2[q]);
            acc2[q] = ffma2(cc.y, av, acc2[q]);
        }
    }

    float accs[4];
    { U64 p; p.u = acc2[0]; accs[0] = p.f.x; accs[1] = p.f.y; }
    { U64 p; p.u = acc2[1]; accs[2] = p.f.x; accs[3] = p.f.y; }

    float res[4];
    #pragma unroll
    for (int q = 0; q < 4; q++) {
        float xs = accs[q];
        int k = 0;
        #pragma unroll
        for (int step = 64; step > 0; step >>= 1) {
            if (k + step <= 64 && s_mt[k + step] <= xs) k += step;
        }
        res[q] = fmaf(s_msa[k], xs, s_msb[k]);
    }
    *(float4*)&out[e] = make_float4(res[0], res[1], res[2], res[3]);
}

// ---------------------------------------------------------------------------
// Launch
// ---------------------------------------------------------------------------
extern "C" void kernel_launch(void* const* d_in, const int* in_sizes, int n_in,
                              void* d_out, int out_size) {
    const float* x      = (const float*)d_in[0];
    const int*   mask   = (const int*)  d_in[1];
    const float* b_fs   = (const float*)d_in[3];
    const float* W_in   = (const float*)d_in[4];
    const float* b_in   = (const float*)d_in[5];
    const float* adj    = (const float*)d_in[6];
    const float* W_gc   = (const float*)d_in[7];
    const float* b_gc   = (const float*)d_in[8];
    const float* W_lo   = (const float*)d_in[9];
    const float* b_lo   = (const float*)d_in[10];
    const float* prelua = (const float*)d_in[11];
    const float* W_ro   = (const float*)d_in[12];
    const float* b_ro   = (const float*)d_in[13];
    const float* W_o1   = (const float*)d_in[14];
    const float* b_o1   = (const float*)d_in[15];
    const float* W_o2   = (const float*)d_in[16];
    const float* b_o2   = (const float*)d_in[17];
    float* out = (float*)d_out;

    cudaFuncSetAttribute(mma_kernel, cudaFuncAttributeMaxDynamicSharedMemorySize, MMA_SMEM);

    coef_kernel<<<1, 64>>>(W_in, b_in, W_gc, b_gc, W_lo, b_lo, W_ro, prelua,
                           W_o1, b_o1, W_o2, b_o2, b_ro);
    prep_kernel<<<1280, 256>>>(adj, x, mask, b_fs);
    mma_kernel<<<128, 512, MMA_SMEM>>>();
    epilogue_kernel<<<ELEMS / 4 / 256, 256>>>(x, mask, b_fs, out);
}

// round 10
// speedup vs baseline: 1.0248x; 1.0248x over previous
#include <cuda_runtime.h>
#include <cuda_bf16.h>
#include <math_constants.h>
#include <cstdint>

// Problem constants
#define BB 8
#define NN 1024
#define TT 64
#define ELEMS (BB*NN*TT)  // 524288

// Scratch (no allocations allowed)
__device__ __nv_bfloat16 g_Ah[1024 * 1024];  // A[m=j][k=i] = adj[i][j], hi part
__device__ __nv_bfloat16 g_Al[1024 * 1024];  // lo part
__device__ __nv_bfloat16 g_Bh[1024 * 1024];  // B[n=c][k=i] = X[i][c], hi part
__device__ __nv_bfloat16 g_Bl[1024 * 1024];  // lo part (x1 half only; mask half exact)
__device__ float g_U[1024 * 1024];           // U[j*1024 + c]
__device__ float g_S[1024];                  // column sums of adj (atomic-accumulated)
// Epilogue coefficient tables
__device__ float g_scd[512];         // [h][8] = r1,r1,r2,r2,r3,r3,r4,r4
__device__ float g_c12[256];         // [h][4] = c1,c1,c2,c2
__device__ float g_r56[128];         // [h][2] = r5,r6
__device__ float g_mt[65];           // sorted MLP breakpoints (1-based)
__device__ float g_msa[65];          // piecewise slope table
__device__ float g_msb[65];          // piecewise intercept table

// ---------- helpers ----------
union U64 { unsigned long long u; float2 f; };

__device__ __forceinline__ unsigned long long ffma2(unsigned long long a,
                                                    unsigned long long b,
                                                    unsigned long long c) {
    unsigned long long d;
    asm("fma.rn.f32x2 %0, %1, %2, %3;" : "=l"(d) : "l"(a), "l"(b), "l"(c));
    return d;
}
__device__ __forceinline__ unsigned long long pack2(float x, float y) {
    U64 u; u.f = make_float2(x, y); return u.u;
}
__device__ __forceinline__ uint32_t smem_u32(const void* p) {
    uint32_t a;
    asm("{ .reg .u64 t; cvta.to.shared.u64 t, %1; cvt.u32.u64 %0, t; }" : "=r"(a) : "l"(p));
    return a;
}
__device__ __forceinline__ void cpasync16(uint32_t s, const void* g) {
    asm volatile("cp.async.cg.shared.global [%0], [%1], 16;" :: "r"(s), "l"(g));
}
#define CP_COMMIT() asm volatile("cp.async.commit_group;" ::: "memory")

__device__ __forceinline__ void ldm_x4(uint32_t& r0, uint32_t& r1, uint32_t& r2,
                                       uint32_t& r3, uint32_t a) {
    asm volatile("ldmatrix.sync.aligned.m8n8.x4.shared.b16 {%0,%1,%2,%3}, [%4];"
                 : "=r"(r0), "=r"(r1), "=r"(r2), "=r"(r3) : "r"(a));
}
__device__ __forceinline__ void mma_bf16(float& c0, float& c1, float& c2, float& c3,
                                         uint32_t a0, uint32_t a1, uint32_t a2, uint32_t a3,
                                         uint32_t b0, uint32_t b1) {
    asm volatile(
        "mma.sync.aligned.m16n8k16.row.col.f32.bf16.bf16.f32 "
        "{%0,%1,%2,%3}, {%4,%5,%6,%7}, {%8,%9}, {%0,%1,%2,%3};"
        : "+f"(c0), "+f"(c1), "+f"(c2), "+f"(c3)
        : "r"(a0), "r"(a1), "r"(a2), "r"(a3), "r"(b0), "r"(b1));
}

// ---------------------------------------------------------------------------
// Kernel 1: fold all linear layers (h == 0 collapse) + build epilogue tables
// Also zeroes g_S for the fused colsum atomics (stream-ordered before prep).
// ---------------------------------------------------------------------------
__global__ void coef_kernel(const float* __restrict__ Win, const float* __restrict__ bin,
                            const float* __restrict__ Wgc, const float* __restrict__ bgc,
                            const float* __restrict__ Wlo, const float* __restrict__ blo,
                            const float* __restrict__ Wro, const float* __restrict__ prelu_a,
                            const float* __restrict__ Wo1, const float* __restrict__ bo1,
                            const float* __restrict__ Wo2, const float* __restrict__ bo2,
                            const float* __restrict__ bro) {
    __shared__ float sA[64], sC[64], sB[64];
    __shared__ float G[6][64];
    __shared__ float st[64], scz[64];
    __shared__ float srt_t[64], srt_a[64], srt_b[64];
    __shared__ int   srt_p[64];
    int t = threadIdx.x;  // 0..63
    for (int i = t; i < 1024; i += 64) g_S[i] = 0.f;
    sA[t] = Win[t * 66 + 0];
    sC[t] = Win[t * 66 + 1];
    sB[t] = bin[t];
    __syncthreads();
    float g1 = 0, g2 = 0, g3 = 0, g4 = 0, g5 = 0, g6 = 0;
    for (int h = 0; h < 64; h++) {
        float w0 = Wgc[t * 128 + h];
        float w1 = Wgc[t * 128 + 64 + h];
        g1 = fmaf(w0, sA[h], g1);
        g2 = fmaf(w0, sC[h], g2);
        g3 = fmaf(w0, sB[h], g3);
        g4 = fmaf(w1, sA[h], g4);
        g5 = fmaf(w1, sC[h], g5);
        g6 = fmaf(w1, sB[h], g6);
    }
    G[0][t] = g1; G[1][t] = g2; G[2][t] = g4;
    G[3][t] = g5; G[4][t] = g6; G[5][t] = g3 + bgc[t];
    __syncthreads();
    float r[6] = {0, 0, 0, 0, 0, 0};
    for (int o = 0; o < 64; o++) {
        float w = Wlo[t * 128 + o];
        r[0] = fmaf(w, G[0][o], r[0]);
        r[1] = fmaf(w, G[1][o], r[1]);
        r[2] = fmaf(w, G[2][o], r[2]);
        r[3] = fmaf(w, G[3][o], r[3]);
        r[4] = fmaf(w, G[4][o], r[4]);
        r[5] = fmaf(w, G[5][o], r[5]);
    }
    r[5] += blo[t];
    g_scd[t * 8 + 0] = r[0]; g_scd[t * 8 + 1] = r[0];
    g_scd[t * 8 + 2] = r[1]; g_scd[t * 8 + 3] = r[1];
    g_scd[t * 8 + 4] = r[2]; g_scd[t * 8 + 5] = r[2];
    g_scd[t * 8 + 6] = r[3]; g_scd[t * 8 + 7] = r[3];
    g_r56[t * 2 + 0] = r[4]; g_r56[t * 2 + 1] = r[5];
    float wr = Wro[t];
    float wp = wr;
    float wn = wr * prelu_a[0];
    float c1 = 0.5f * (wp + wn);
    float c2 = 0.5f * (wp - wn);
    g_c12[t * 4 + 0] = c1; g_c12[t * 4 + 1] = c1;
    g_c12[t * 4 + 2] = c2; g_c12[t * 4 + 3] = c2;

    // piecewise-linear MLP tables
    float s1 = Wo1[t];
    float s2p = fmaf(s1, bro[0], bo1[t]);
    float s3 = Wo2[t];
    float tf, af, bf, cz = 0.f;
    int isP;
    if (s1 > 0.f)      { tf = -s2p / s1; isP = 1; af = s3 * s1; bf = s3 * s2p; }
    else if (s1 < 0.f) { tf = -s2p / s1; isP = 0; af = s3 * s1; bf = s3 * s2p; }
    else               { tf = CUDART_INF_F; isP = 0; af = 0.f; bf = 0.f;
                         cz = s3 * fmaxf(s2p, 0.f); }
    st[t] = tf; scz[t] = cz;
    __syncthreads();
    int rank = 0;
    for (int g = 0; g < 64; g++) {
        float tg = st[g];
        if (tg < tf || (tg == tf && g < t)) rank++;
    }
    srt_t[rank] = tf; srt_a[rank] = af; srt_b[rank] = bf; srt_p[rank] = isP;
    __syncthreads();
    float C0 = bo2[0];
    for (int g = 0; g < 64; g++) C0 += scz[g];
    for (int k = t; k <= 64; k += 64) {
        float A = 0.f, Bv = 0.f;
        for (int i = 0; i < 64; i++) {
            bool act = srt_p[i] ? (i < k) : (i >= k);
            if (act) { A += srt_a[i]; Bv += srt_b[i]; }
        }
        g_msa[k] = A;
        g_msb[k] = Bv + C0;
    }
    if (t < 64) g_mt[t + 1] = srt_t[t];
    if (t == 0) g_mt[0] = -CUDART_INF_F;
}

// ---------------------------------------------------------------------------
// Kernel 2 (fused prep): blocks 0..1023 convert adj -> Ah/Al (+colsum atomics);
// blocks 1024..1279 convert x/mask -> Bh/Bl.
// ---------------------------------------------------------------------------
__global__ __launch_bounds__(256) void prep_kernel(const float* __restrict__ adj,
                                                   const float* __restrict__ x,
                                                   const int* __restrict__ mask,
                                                   const float* __restrict__ bfs) {
    int tid = threadIdx.x;
    if (blockIdx.x < 1024) {
        __shared__ float tile[32][33];
        int tx = tid & 31, ty = tid >> 5;  // 32 x 8
        int j0 = (blockIdx.x & 31) * 32, i0 = (blockIdx.x >> 5) * 32;
        #pragma unroll
        for (int s = 0; s < 4; s++)
            tile[ty + 8 * s][tx] = adj[(i0 + ty + 8 * s) * 1024 + j0 + tx];
        __syncthreads();
        #pragma unroll
        for (int s = 0; s < 4; s++) {
            float v = tile[tx][ty + 8 * s];
            __nv_bfloat16 h = __float2bfloat16_rn(v);
            __nv_bfloat16 l = __float2bfloat16_rn(v - __bfloat162float(h));
            int idx = (j0 + ty + 8 * s) * 1024 + i0 + tx;
            g_Ah[idx] = h;
            g_Al[idx] = l;
        }
        if (ty == 0) {
            float s = 0.f;
            #pragma unroll
            for (int r = 0; r < 32; r++) s += tile[r][tx];
            atomicAdd(&g_S[j0 + tx], s);
        }
    } else {
        __shared__ float sx[32][65];
        __shared__ float sm[32][65];
        int idx = blockIdx.x - 1024;       // 0..255
        int b = idx >> 5, i0 = (idx & 31) * 32;
        int r = tid >> 3;
        int c8 = (tid & 7) * 8;
        int base = (b * 1024 + i0 + r) * 64 + c8;
        {
            float4 v0 = *(const float4*)&x[base];
            float4 v1 = *(const float4*)&x[base + 4];
            int4 m0v = *(const int4*)&mask[base];
            int4 m1v = *(const int4*)&mask[base + 4];
            sx[r][c8 + 0] = v0.x; sx[r][c8 + 1] = v0.y; sx[r][c8 + 2] = v0.z; sx[r][c8 + 3] = v0.w;
            sx[r][c8 + 4] = v1.x; sx[r][c8 + 5] = v1.y; sx[r][c8 + 6] = v1.z; sx[r][c8 + 7] = v1.w;
            sm[r][c8 + 0] = (float)m0v.x; sm[r][c8 + 1] = (float)m0v.y;
            sm[r][c8 + 2] = (float)m0v.z; sm[r][c8 + 3] = (float)m0v.w;
            sm[r][c8 + 4] = (float)m1v.x; sm[r][c8 + 5] = (float)m1v.y;
            sm[r][c8 + 6] = (float)m1v.z; sm[r][c8 + 7] = (float)m1v.w;
        }
        __syncthreads();
        float bfs0 = bfs[0];
        int t = tid >> 2;
        int iq = (tid & 3) * 8;
        __align__(16) __nv_bfloat16 hh[8], ll[8], mh[8];
        #pragma unroll
        for (int q = 0; q < 8; q++) {
            float mv = sm[iq + q][t];
            float xv = sx[iq + q][t];
            float x1 = (mv != 0.0f) ? xv : bfs0;
            __nv_bfloat16 h = __float2bfloat16_rn(x1);
            hh[q] = h;
            ll[q] = __float2bfloat16_rn(x1 - __bfloat162float(h));
            mh[q] = __float2bfloat16_rn(mv);
        }
        int c1 = b * 64 + t;
        int row1 = c1 * 1024 + i0 + iq;
        *(uint4*)&g_Bh[row1] = *(uint4*)&hh[0];
        *(uint4*)&g_Bl[row1] = *(uint4*)&ll[0];
        int row2 = (512 + c1) * 1024 + i0 + iq;
        *(uint4*)&g_Bh[row2] = *(uint4*)&mh[0];
    }
}

// ---------------------------------------------------------------------------
// Kernel 3: bf16 tensor-core GEMM (round-8 config: 256 thr / 8 warps,
// warp tile 32m x 32n-paired, fused 3-term accumulation, 3-stage pipeline,
// x4-ldmatrix, ks-level frag pipelining). CTA tile M=64 x N=128 paired.
// ---------------------------------------------------------------------------
#define ROWB 144
#define AH_OFF 0
#define AL_OFF (64 * ROWB)         // 9216
#define BH_OFF (128 * ROWB)        // 18432
#define BL_OFF (256 * ROWB)        // 36864
#define BUFB   (320 * ROWB)        // 46080
#define MMA_SMEM (3 * BUFB)        // 138240

struct Frags {
    uint32_t ah[2][4], al[2][4];
    uint32_t bh0[4], bh1[4], bl0[2], bl1[2];
};

__device__ __forceinline__ void load_frags(Frags& f, uint32_t sb, int ks,
                                           uint32_t a_rel, uint32_t bh_b0,
                                           uint32_t bh_b1, uint32_t bl_b) {
    uint32_t o = ks * 32;
    ldm_x4(f.bh0[0], f.bh1[0], f.bh0[1], f.bh1[1], sb + bh_b0 + o);
    ldm_x4(f.bh0[2], f.bh1[2], f.bh0[3], f.bh1[3], sb + bh_b1 + o);
    ldm_x4(f.bl0[0], f.bl1[0], f.bl0[1], f.bl1[1], sb + bl_b + o);
    ldm_x4(f.ah[0][0], f.ah[0][1], f.ah[0][2], f.ah[0][3], sb + AH_OFF + a_rel + o);
    ldm_x4(f.ah[1][0], f.ah[1][1], f.ah[1][2], f.ah[1][3], sb + AH_OFF + a_rel + 16 * ROWB + o);
    ldm_x4(f.al[0][0], f.al[0][1], f.al[0][2], f.al[0][3], sb + AL_OFF + a_rel + o);
    ldm_x4(f.al[1][0], f.al[1][1], f.al[1][2], f.al[1][3], sb + AL_OFF + a_rel + 16 * ROWB + o);
}

__global__ __launch_bounds__(256) void mma_kernel() {
    extern __shared__ __align__(16) char smem[];
    int tid = threadIdx.x;
    int wid = tid >> 5, lane = tid & 31;
    int m0 = (blockIdx.x >> 3) * 64;
    int pn64 = (blockIdx.x & 7) * 64;
    uint32_t sbase = smem_u32(smem);

    uint32_t soff[10];
    const __nv_bfloat16* gp[10];
    #pragma unroll
    for (int q = 0; q < 10; q++) {
        int c = tid + 256 * q;          // 0..2559
        int row = c >> 3, col = c & 7;
        soff[q] = row * ROWB + col * 16;
        if (row < 64) {
            gp[q] = g_Ah + (m0 + row) * 1024 + col * 8;
        } else if (row < 128) {
            gp[q] = g_Al + (m0 + row - 64) * 1024 + col * 8;
        } else if (row < 256) {
            int r = row - 128;
            int gcol = (r < 64) ? (pn64 + r) : (512 + pn64 + r - 64);
            gp[q] = g_Bh + gcol * 1024 + col * 8;
        } else {
            gp[q] = g_Bl + (pn64 + row - 256) * 1024 + col * 8;
        }
    }

    float acc[2][4][4];
    #pragma unroll
    for (int mt = 0; mt < 2; mt++)
        #pragma unroll
        for (int nt = 0; nt < 4; nt++)
            #pragma unroll
            for (int q = 0; q < 4; q++) acc[mt][nt][q] = 0.f;

    int warp_m = (wid >> 2) * 32;
    int w2 = wid & 3;
    uint32_t a_rel = (warp_m + (lane & 15)) * ROWB + ((lane >> 4) & 1) * 16;
    uint32_t x4row = (lane & 7) + ((lane >> 4) & 1) * 8;
    uint32_t x4chk = ((lane >> 3) & 1) * 16;
    uint32_t bh_b0 = BH_OFF + (w2 * 16 + x4row) * ROWB + x4chk;
    uint32_t bh_b1 = BH_OFF + (64 + w2 * 16 + x4row) * ROWB + x4chk;
    uint32_t bl_b  = BL_OFF + (w2 * 16 + x4row) * ROWB + x4chk;

    #pragma unroll
    for (int q = 0; q < 10; q++) cpasync16(sbase + soff[q], gp[q]);
    CP_COMMIT();
    #pragma unroll
    for (int q = 0; q < 10; q++) cpasync16(sbase + BUFB + soff[q], gp[q] + 64);
    CP_COMMIT();

    for (int it = 0; it < 16; it++) {
        int buf = it % 3;
        if (it + 2 < 16) {
            int k0 = (it + 2) * 64;
            uint32_t sb = sbase + ((it + 2) % 3) * BUFB;
            #pragma unroll
            for (int q = 0; q < 10; q++) cpasync16(sb + soff[q], gp[q] + k0);
            CP_COMMIT();
            asm volatile("cp.async.wait_group 2;" ::: "memory");
        } else if (it == 14) {
            asm volatile("cp.async.wait_group 1;" ::: "memory");
        } else {
            asm volatile("cp.async.wait_group 0;" ::: "memory");
        }
        __syncthreads();

        uint32_t sb = sbase + buf * BUFB;
        Frags F;
        load_frags(F, sb, 0, a_rel, bh_b0, bh_b1, bl_b);
        #pragma unroll
        for (int ks = 0; ks < 4; ks++) {
            Frags Fn;
            if (ks < 3) load_frags(Fn, sb, ks + 1, a_rel, bh_b0, bh_b1, bl_b);
            #pragma unroll
            for (int mt = 0; mt < 2; mt++)
                #pragma unroll
                for (int nt = 0; nt < 4; nt++)
                    mma_bf16(acc[mt][nt][0], acc[mt][nt][1], acc[mt][nt][2], acc[mt][nt][3],
                             F.ah[mt][0], F.ah[mt][1], F.ah[mt][2], F.ah[mt][3],
                             F.bh0[nt], F.bh1[nt]);
            #pragma unroll
            for (int mt = 0; mt < 2; mt++)
                #pragma unroll
                for (int nt = 0; nt < 2; nt++)
                    mma_bf16(acc[mt][nt][0], acc[mt][nt][1], acc[mt][nt][2], acc[mt][nt][3],
                             F.ah[mt][0], F.ah[mt][1], F.ah[mt][2], F.ah[mt][3],
                             F.bl0[nt], F.bl1[nt]);
            #pragma unroll
            for (int mt = 0; mt < 2; mt++)
                #pragma unroll
                for (int nt = 0; nt < 4; nt++)
                    mma_bf16(acc[mt][nt][0], acc[mt][nt][1], acc[mt][nt][2], acc[mt][nt][3],
                             F.al[mt][0], F.al[mt][1], F.al[mt][2], F.al[mt][3],
                             F.bh0[nt], F.bh1[nt]);
            if (ks < 3) F = Fn;
        }
        __syncthreads();
    }

    int r0 = m0 + warp_m + (lane >> 2);
    #pragma unroll
    for (int mt = 0; mt < 2; mt++) {
        #pragma unroll
        for (int nt = 0; nt < 4; nt++) {
            int cb = (nt >= 2 ? 512 : 0) + pn64 + w2 * 16 + (nt & 1) * 8 + (lane & 3) * 2;
            *(float2*)&g_U[(size_t)(r0 + mt * 16) * 1024 + cb] =
                make_float2(acc[mt][nt][0], acc[mt][nt][1]);
            *(float2*)&g_U[(size_t)(r0 + mt * 16 + 8) * 1024 + cb] =
                make_float2(acc[mt][nt][2], acc[mt][nt][3]);
        }
    }
}

// ---------------------------------------------------------------------------
// Kernel 4: pointwise epilogue, 16 elements/thread (coeff reads amortized 4x)
// 128 threads x 256 blocks.
// ---------------------------------------------------------------------------
__global__ __launch_bounds__(128) void epilogue_kernel(
    const float* __restrict__ x, const int* __restrict__ mask,
    const float* __restrict__ bfs, float* __restrict__ out) {
    __shared__ float s_scd[512];
    __shared__ float s_c12[256];
    __shared__ float s_r56[128];
    __shared__ float s_mt[65], s_msa[65], s_msb[65];
    int tid = threadIdx.x;
    for (int i = tid; i < 512; i += 128) s_scd[i] = g_scd[i];
    for (int i = tid; i < 256; i += 128) s_c12[i] = g_c12[i];
    s_r56[tid] = g_r56[tid];
    if (tid < 65) { s_mt[tid] = g_mt[tid]; s_msa[tid] = g_msa[tid]; s_msb[tid] = g_msb[tid]; }
    __syncthreads();
    float bfs0 = bfs[0];

    int gid = blockIdx.x * 128 + tid;   // 0..32767
    int e = gid * 16;
    int b = e >> 16;
    int rem = e & 65535;
    int j = rem >> 6;
    int tt = rem & 63;
    int c = b * 64 + tt;
    size_t ubase = (size_t)j * 1024 + c;
    float sj = g_S[j];

    unsigned long long x1p[8], mfp[8], u1p[8], u2p[8];
    #pragma unroll
    for (int g = 0; g < 4; g++) {
        float4 xv = *(const float4*)&x[e + g * 4];
        int4 mv = *(const int4*)&mask[e + g * 4];
        float4 u1v = *(const float4*)&g_U[ubase + g * 4];
        float4 u2v = *(const float4*)&g_U[ubase + 512 + g * 4];
        float a0 = mv.x ? xv.x : bfs0;
        float a1 = mv.y ? xv.y : bfs0;
        float a2 = mv.z ? xv.z : bfs0;
        float a3 = mv.w ? xv.w : bfs0;
        x1p[g * 2]     = pack2(a0, a1);
        x1p[g * 2 + 1] = pack2(a2, a3);
        mfp[g * 2]     = pack2((float)mv.x, (float)mv.y);
        mfp[g * 2 + 1] = pack2((float)mv.z, (float)mv.w);
        u1p[g * 2]     = pack2(u1v.x, u1v.y);
        u1p[g * 2 + 1] = pack2(u1v.z, u1v.w);
        u2p[g * 2]     = pack2(u2v.x, u2v.y);
        u2p[g * 2 + 1] = pack2(u2v.z, u2v.w);
    }

    unsigned long long acc2[8];
    #pragma unroll
    for (int q = 0; q < 8; q++) acc2[q] = 0ULL;

    #pragma unroll 2
    for (int h = 0; h < 64; h++) {
        ulonglong2 r12 = *(const ulonglong2*)&s_scd[h * 8];
        ulonglong2 r34 = *(const ulonglong2*)&s_scd[h * 8 + 4];
        float2 r56v = *(const float2*)&s_r56[h * 2];
        ulonglong2 cc = *(const ulonglong2*)&s_c12[h * 4];
        float base = fmaf(r56v.x, sj, r56v.y);
        unsigned long long base2 = pack2(base, base);
        #pragma unroll
        for (int q = 0; q < 8; q++) {
            unsigned long long v =
                ffma2(r12.x, x1p[q],
                ffma2(r12.y, mfp[q],
                ffma2(r34.x, u1p[q],
                ffma2(r34.y, u2p[q], base2))));
            unsigned long long av = v & 0x7fffffff7fffffffULL;
            acc2[q] = ffma2(cc.x, v, acc2[q]);
            acc2[q] = ffma2(cc.y, av, acc2[q]);
        }
    }

    #pragma unroll
    for (int g = 0; g < 4; g++) {
        float accs[4];
        { U64 p; p.u = acc2[g * 2];     accs[0] = p.f.x; accs[1] = p.f.y; }
        { U64 p; p.u = acc2[g * 2 + 1]; accs[2] = p.f.x; accs[3] = p.f.y; }
        float res[4];
        #pragma unroll
        for (int q = 0; q < 4; q++) {
            float xs = accs[q];
            int k = 0;
            #pragma unroll
            for (int step = 64; step > 0; step >>= 1) {
                if (k + step <= 64 && s_mt[k + step] <= xs) k += step;
            }
            res[q] = fmaf(s_msa[k], xs, s_msb[k]);
        }
        *(float4*)&out[e + g * 4] = make_float4(res[0], res[1], res[2], res[3]);
    }
}

// ---------------------------------------------------------------------------
// Launch
// ---------------------------------------------------------------------------
extern "C" void kernel_launch(void* const* d_in, const int* in_sizes, int n_in,
                              void* d_out, int out_size) {
    const float* x      = (const float*)d_in[0];
    const int*   mask   = (const int*)  d_in[1];
    const float* b_fs   = (const float*)d_in[3];
    const float* W_in   = (const float*)d_in[4];
    const float* b_in   = (const float*)d_in[5];
    const float* adj    = (const float*)d_in[6];
    const float* W_gc   = (const float*)d_in[7];
    const float* b_gc   = (const float*)d_in[8];
    const float* W_lo   = (const float*)d_in[9];
    const float* b_lo   = (const float*)d_in[10];
    const float* prelua = (const float*)d_in[11];
    const float* W_ro   = (const float*)d_in[12];
    const float* b_ro   = (const float*)d_in[13];
    const float* W_o1   = (const float*)d_in[14];
    const float* b_o1   = (const float*)d_in[15];
    const float* W_o2   = (const float*)d_in[16];
    const float* b_o2   = (const float*)d_in[17];
    float* out = (float*)d_out;

    cudaFuncSetAttribute(mma_kernel, cudaFuncAttributeMaxDynamicSharedMemorySize, MMA_SMEM);

    coef_kernel<<<1, 64>>>(W_in, b_in, W_gc, b_gc, W_lo, b_lo, W_ro, prelua,
                           W_o1, b_o1, W_o2, b_o2, b_ro);
    prep_kernel<<<1280, 256>>>(adj, x, mask, b_fs);
    mma_kernel<<<128, 256, MMA_SMEM>>>();
    epilogue_kernel<<<256, 128>>>(x, mask, b_fs, out);
}

// round 11
// speedup vs baseline: 1.0422x; 1.0170x over previous
#include <cuda_runtime.h>
#include <cuda_bf16.h>
#include <math_constants.h>
#include <cstdint>

// Problem constants
#define BB 8
#define NN 1024
#define TT 64
#define ELEMS (BB*NN*TT)  // 524288

// Scratch (no allocations allowed)
__device__ __nv_bfloat16 g_Ah[1024 * 1024];  // A[m=j][k=i] = adj[i][j], hi part
__device__ __nv_bfloat16 g_Al[1024 * 1024];  // lo part
__device__ __nv_bfloat16 g_Bh[1024 * 1024];  // B[n=c][k=i] = X[i][c], hi part
__device__ __nv_bfloat16 g_Bl[1024 * 1024];  // lo part (x1 half only; mask half exact)
__device__ float g_U[1024 * 1024];           // U[j*1024 + c]
__device__ float g_S[1024];                  // column sums of adj (atomic-accumulated)
// Epilogue coefficient tables
__device__ float g_scd[512];         // [h][8] = r1,r1,r2,r2,r3,r3,r4,r4
__device__ float g_c12[256];         // [h][4] = c1,c1,c2,c2
__device__ float g_r56[128];         // [h][2] = r5,r6
__device__ float g_mt[65];           // sorted MLP breakpoints (1-based)
__device__ float g_msa[65];          // piecewise slope table
__device__ float g_msb[65];          // piecewise intercept table

// ---------- helpers ----------
union U64 { unsigned long long u; float2 f; };

__device__ __forceinline__ unsigned long long ffma2(unsigned long long a,
                                                    unsigned long long b,
                                                    unsigned long long c) {
    unsigned long long d;
    asm("fma.rn.f32x2 %0, %1, %2, %3;" : "=l"(d) : "l"(a), "l"(b), "l"(c));
    return d;
}
__device__ __forceinline__ unsigned long long pack2(float x, float y) {
    U64 u; u.f = make_float2(x, y); return u.u;
}
__device__ __forceinline__ uint32_t smem_u32(const void* p) {
    uint32_t a;
    asm("{ .reg .u64 t; cvta.to.shared.u64 t, %1; cvt.u32.u64 %0, t; }" : "=r"(a) : "l"(p));
    return a;
}
__device__ __forceinline__ void cpasync16(uint32_t s, const void* g) {
    asm volatile("cp.async.cg.shared.global [%0], [%1], 16;" :: "r"(s), "l"(g));
}
#define CP_COMMIT() asm volatile("cp.async.commit_group;" ::: "memory")

__device__ __forceinline__ void ldm_x4(uint32_t& r0, uint32_t& r1, uint32_t& r2,
                                       uint32_t& r3, uint32_t a) {
    asm volatile("ldmatrix.sync.aligned.m8n8.x4.shared.b16 {%0,%1,%2,%3}, [%4];"
                 : "=r"(r0), "=r"(r1), "=r"(r2), "=r"(r3) : "r"(a));
}
__device__ __forceinline__ void mma_bf16(float& c0, float& c1, float& c2, float& c3,
                                         uint32_t a0, uint32_t a1, uint32_t a2, uint32_t a3,
                                         uint32_t b0, uint32_t b1) {
    asm volatile(
        "mma.sync.aligned.m16n8k16.row.col.f32.bf16.bf16.f32 "
        "{%0,%1,%2,%3}, {%4,%5,%6,%7}, {%8,%9}, {%0,%1,%2,%3};"
        : "+f"(c0), "+f"(c1), "+f"(c2), "+f"(c3)
        : "r"(a0), "r"(a1), "r"(a2), "r"(a3), "r"(b0), "r"(b1));
}

// ---------------------------------------------------------------------------
// Kernel 1: fold all linear layers (h == 0 collapse) + build epilogue tables
// Also zeroes g_S for the fused colsum atomics (stream-ordered before prep).
// ---------------------------------------------------------------------------
__global__ void coef_kernel(const float* __restrict__ Win, const float* __restrict__ bin,
                            const float* __restrict__ Wgc, const float* __restrict__ bgc,
                            const float* __restrict__ Wlo, const float* __restrict__ blo,
                            const float* __restrict__ Wro, const float* __restrict__ prelu_a,
                            const float* __restrict__ Wo1, const float* __restrict__ bo1,
                            const float* __restrict__ Wo2, const float* __restrict__ bo2,
                            const float* __restrict__ bro) {
    __shared__ float sA[64], sC[64], sB[64];
    __shared__ float G[6][64];
    __shared__ float st[64], scz[64];
    __shared__ float srt_t[64], srt_a[64], srt_b[64];
    __shared__ int   srt_p[64];
    int t = threadIdx.x;  // 0..63
    for (int i = t; i < 1024; i += 64) g_S[i] = 0.f;
    sA[t] = Win[t * 66 + 0];
    sC[t] = Win[t * 66 + 1];
    sB[t] = bin[t];
    __syncthreads();
    float g1 = 0, g2 = 0, g3 = 0, g4 = 0, g5 = 0, g6 = 0;
    for (int h = 0; h < 64; h++) {
        float w0 = Wgc[t * 128 + h];
        float w1 = Wgc[t * 128 + 64 + h];
        g1 = fmaf(w0, sA[h], g1);
        g2 = fmaf(w0, sC[h], g2);
        g3 = fmaf(w0, sB[h], g3);
        g4 = fmaf(w1, sA[h], g4);
        g5 = fmaf(w1, sC[h], g5);
        g6 = fmaf(w1, sB[h], g6);
    }
    G[0][t] = g1; G[1][t] = g2; G[2][t] = g4;
    G[3][t] = g5; G[4][t] = g6; G[5][t] = g3 + bgc[t];
    __syncthreads();
    float r[6] = {0, 0, 0, 0, 0, 0};
    for (int o = 0; o < 64; o++) {
        float w = Wlo[t * 128 + o];
        r[0] = fmaf(w, G[0][o], r[0]);
        r[1] = fmaf(w, G[1][o], r[1]);
        r[2] = fmaf(w, G[2][o], r[2]);
        r[3] = fmaf(w, G[3][o], r[3]);
        r[4] = fmaf(w, G[4][o], r[4]);
        r[5] = fmaf(w, G[5][o], r[5]);
    }
    r[5] += blo[t];
    g_scd[t * 8 + 0] = r[0]; g_scd[t * 8 + 1] = r[0];
    g_scd[t * 8 + 2] = r[1]; g_scd[t * 8 + 3] = r[1];
    g_scd[t * 8 + 4] = r[2]; g_scd[t * 8 + 5] = r[2];
    g_scd[t * 8 + 6] = r[3]; g_scd[t * 8 + 7] = r[3];
    g_r56[t * 2 + 0] = r[4]; g_r56[t * 2 + 1] = r[5];
    float wr = Wro[t];
    float wp = wr;
    float wn = wr * prelu_a[0];
    float c1 = 0.5f * (wp + wn);
    float c2 = 0.5f * (wp - wn);
    g_c12[t * 4 + 0] = c1; g_c12[t * 4 + 1] = c1;
    g_c12[t * 4 + 2] = c2; g_c12[t * 4 + 3] = c2;

    // piecewise-linear MLP tables
    float s1 = Wo1[t];
    float s2p = fmaf(s1, bro[0], bo1[t]);
    float s3 = Wo2[t];
    float tf, af, bf, cz = 0.f;
    int isP;
    if (s1 > 0.f)      { tf = -s2p / s1; isP = 1; af = s3 * s1; bf = s3 * s2p; }
    else if (s1 < 0.f) { tf = -s2p / s1; isP = 0; af = s3 * s1; bf = s3 * s2p; }
    else               { tf = CUDART_INF_F; isP = 0; af = 0.f; bf = 0.f;
                         cz = s3 * fmaxf(s2p, 0.f); }
    st[t] = tf; scz[t] = cz;
    __syncthreads();
    int rank = 0;
    for (int g = 0; g < 64; g++) {
        float tg = st[g];
        if (tg < tf || (tg == tf && g < t)) rank++;
    }
    srt_t[rank] = tf; srt_a[rank] = af; srt_b[rank] = bf; srt_p[rank] = isP;
    __syncthreads();
    float C0 = bo2[0];
    for (int g = 0; g < 64; g++) C0 += scz[g];
    for (int k = t; k <= 64; k += 64) {
        float A = 0.f, Bv = 0.f;
        for (int i = 0; i < 64; i++) {
            bool act = srt_p[i] ? (i < k) : (i >= k);
            if (act) { A += srt_a[i]; Bv += srt_b[i]; }
        }
        g_msa[k] = A;
        g_msb[k] = Bv + C0;
    }
    if (t < 64) g_mt[t + 1] = srt_t[t];
    if (t == 0) g_mt[0] = -CUDART_INF_F;
}

// ---------------------------------------------------------------------------
// Kernel 2 (fused prep): blocks 0..1023 convert adj -> Ah/Al (+colsum atomics);
// blocks 1024..1279 convert x/mask -> Bh/Bl.
// ---------------------------------------------------------------------------
__global__ __launch_bounds__(256) void prep_kernel(const float* __restrict__ adj,
                                                   const float* __restrict__ x,
                                                   const int* __restrict__ mask,
                                                   const float* __restrict__ bfs) {
    int tid = threadIdx.x;
    if (blockIdx.x < 1024) {
        __shared__ float tile[32][33];
        int tx = tid & 31, ty = tid >> 5;  // 32 x 8
        int j0 = (blockIdx.x & 31) * 32, i0 = (blockIdx.x >> 5) * 32;
        #pragma unroll
        for (int s = 0; s < 4; s++)
            tile[ty + 8 * s][tx] = adj[(i0 + ty + 8 * s) * 1024 + j0 + tx];
        __syncthreads();
        #pragma unroll
        for (int s = 0; s < 4; s++) {
            float v = tile[tx][ty + 8 * s];
            __nv_bfloat16 h = __float2bfloat16_rn(v);
            __nv_bfloat16 l = __float2bfloat16_rn(v - __bfloat162float(h));
            int idx = (j0 + ty + 8 * s) * 1024 + i0 + tx;
            g_Ah[idx] = h;
            g_Al[idx] = l;
        }
        if (ty == 0) {
            float s = 0.f;
            #pragma unroll
            for (int r = 0; r < 32; r++) s += tile[r][tx];
            atomicAdd(&g_S[j0 + tx], s);
        }
    } else {
        __shared__ float sx[32][65];
        __shared__ float sm[32][65];
        int idx = blockIdx.x - 1024;       // 0..255
        int b = idx >> 5, i0 = (idx & 31) * 32;
        int r = tid >> 3;
        int c8 = (tid & 7) * 8;
        int base = (b * 1024 + i0 + r) * 64 + c8;
        {
            float4 v0 = *(const float4*)&x[base];
            float4 v1 = *(const float4*)&x[base + 4];
            int4 m0v = *(const int4*)&mask[base];
            int4 m1v = *(const int4*)&mask[base + 4];
            sx[r][c8 + 0] = v0.x; sx[r][c8 + 1] = v0.y; sx[r][c8 + 2] = v0.z; sx[r][c8 + 3] = v0.w;
            sx[r][c8 + 4] = v1.x; sx[r][c8 + 5] = v1.y; sx[r][c8 + 6] = v1.z; sx[r][c8 + 7] = v1.w;
            sm[r][c8 + 0] = (float)m0v.x; sm[r][c8 + 1] = (float)m0v.y;
            sm[r][c8 + 2] = (float)m0v.z; sm[r][c8 + 3] = (float)m0v.w;
            sm[r][c8 + 4] = (float)m1v.x; sm[r][c8 + 5] = (float)m1v.y;
            sm[r][c8 + 6] = (float)m1v.z; sm[r][c8 + 7] = (float)m1v.w;
        }
        __syncthreads();
        float bfs0 = bfs[0];
        int t = tid >> 2;
        int iq = (tid & 3) * 8;
        __align__(16) __nv_bfloat16 hh[8], ll[8], mh[8];
        #pragma unroll
        for (int q = 0; q < 8; q++) {
            float mv = sm[iq + q][t];
            float xv = sx[iq + q][t];
            float x1 = (mv != 0.0f) ? xv : bfs0;
            __nv_bfloat16 h = __float2bfloat16_rn(x1);
            hh[q] = h;
            ll[q] = __float2bfloat16_rn(x1 - __bfloat162float(h));
            mh[q] = __float2bfloat16_rn(mv);
        }
        int c1 = b * 64 + t;
        int row1 = c1 * 1024 + i0 + iq;
        *(uint4*)&g_Bh[row1] = *(uint4*)&hh[0];
        *(uint4*)&g_Bl[row1] = *(uint4*)&ll[0];
        int row2 = (512 + c1) * 1024 + i0 + iq;
        *(uint4*)&g_Bh[row2] = *(uint4*)&mh[0];
    }
}

// ---------------------------------------------------------------------------
// Kernel 3: bf16 tensor-core GEMM (round-8 config: 256 thr / 8 warps,
// warp tile 32m x 32n-paired, fused 3-term accumulation, 3-stage pipeline,
// x4-ldmatrix, ks-level frag pipelining). CTA tile M=64 x N=128 paired.
// ---------------------------------------------------------------------------
#define ROWB 144
#define AH_OFF 0
#define AL_OFF (64 * ROWB)         // 9216
#define BH_OFF (128 * ROWB)        // 18432
#define BL_OFF (256 * ROWB)        // 36864
#define BUFB   (320 * ROWB)        // 46080
#define MMA_SMEM (3 * BUFB)        // 138240

struct Frags {
    uint32_t ah[2][4], al[2][4];
    uint32_t bh0[4], bh1[4], bl0[2], bl1[2];
};

__device__ __forceinline__ void load_frags(Frags& f, uint32_t sb, int ks,
                                           uint32_t a_rel, uint32_t bh_b0,
                                           uint32_t bh_b1, uint32_t bl_b) {
    uint32_t o = ks * 32;
    ldm_x4(f.bh0[0], f.bh1[0], f.bh0[1], f.bh1[1], sb + bh_b0 + o);
    ldm_x4(f.bh0[2], f.bh1[2], f.bh0[3], f.bh1[3], sb + bh_b1 + o);
    ldm_x4(f.bl0[0], f.bl1[0], f.bl0[1], f.bl1[1], sb + bl_b + o);
    ldm_x4(f.ah[0][0], f.ah[0][1], f.ah[0][2], f.ah[0][3], sb + AH_OFF + a_rel + o);
    ldm_x4(f.ah[1][0], f.ah[1][1], f.ah[1][2], f.ah[1][3], sb + AH_OFF + a_rel + 16 * ROWB + o);
    ldm_x4(f.al[0][0], f.al[0][1], f.al[0][2], f.al[0][3], sb + AL_OFF + a_rel + o);
    ldm_x4(f.al[1][0], f.al[1][1], f.al[1][2], f.al[1][3], sb + AL_OFF + a_rel + 16 * ROWB + o);
}

__global__ __launch_bounds__(256) void mma_kernel() {
    extern __shared__ __align__(16) char smem[];
    int tid = threadIdx.x;
    int wid = tid >> 5, lane = tid & 31;
    int m0 = (blockIdx.x >> 3) * 64;
    int pn64 = (blockIdx.x & 7) * 64;
    uint32_t sbase = smem_u32(smem);

    uint32_t soff[10];
    const __nv_bfloat16* gp[10];
    #pragma unroll
    for (int q = 0; q < 10; q++) {
        int c = tid + 256 * q;          // 0..2559
        int row = c >> 3, col = c & 7;
        soff[q] = row * ROWB + col * 16;
        if (row < 64) {
            gp[q] = g_Ah + (m0 + row) * 1024 + col * 8;
        } else if (row < 128) {
            gp[q] = g_Al + (m0 + row - 64) * 1024 + col * 8;
        } else if (row < 256) {
            int r = row - 128;
            int gcol = (r < 64) ? (pn64 + r) : (512 + pn64 + r - 64);
            gp[q] = g_Bh + gcol * 1024 + col * 8;
        } else {
            gp[q] = g_Bl + (pn64 + row - 256) * 1024 + col * 8;
        }
    }

    float acc[2][4][4];
    #pragma unroll
    for (int mt = 0; mt < 2; mt++)
        #pragma unroll
        for (int nt = 0; nt < 4; nt++)
            #pragma unroll
            for (int q = 0; q < 4; q++) acc[mt][nt][q] = 0.f;

    int warp_m = (wid >> 2) * 32;
    int w2 = wid & 3;
    uint32_t a_rel = (warp_m + (lane & 15)) * ROWB + ((lane >> 4) & 1) * 16;
    uint32_t x4row = (lane & 7) + ((lane >> 4) & 1) * 8;
    uint32_t x4chk = ((lane >> 3) & 1) * 16;
    uint32_t bh_b0 = BH_OFF + (w2 * 16 + x4row) * ROWB + x4chk;
    uint32_t bh_b1 = BH_OFF + (64 + w2 * 16 + x4row) * ROWB + x4chk;
    uint32_t bl_b  = BL_OFF + (w2 * 16 + x4row) * ROWB + x4chk;

    #pragma unroll
    for (int q = 0; q < 10; q++) cpasync16(sbase + soff[q], gp[q]);
    CP_COMMIT();
    #pragma unroll
    for (int q = 0; q < 10; q++) cpasync16(sbase + BUFB + soff[q], gp[q] + 64);
    CP_COMMIT();

    for (int it = 0; it < 16; it++) {
        int buf = it % 3;
        if (it + 2 < 16) {
            int k0 = (it + 2) * 64;
            uint32_t sb = sbase + ((it + 2) % 3) * BUFB;
            #pragma unroll
            for (int q = 0; q < 10; q++) cpasync16(sb + soff[q], gp[q] + k0);
            CP_COMMIT();
            asm volatile("cp.async.wait_group 2;" ::: "memory");
        } else if (it == 14) {
            asm volatile("cp.async.wait_group 1;" ::: "memory");
        } else {
            asm volatile("cp.async.wait_group 0;" ::: "memory");
        }
        __syncthreads();

        uint32_t sb = sbase + buf * BUFB;
        Frags F;
        load_frags(F, sb, 0, a_rel, bh_b0, bh_b1, bl_b);
        #pragma unroll
        for (int ks = 0; ks < 4; ks++) {
            Frags Fn;
            if (ks < 3) load_frags(Fn, sb, ks + 1, a_rel, bh_b0, bh_b1, bl_b);
            #pragma unroll
            for (int mt = 0; mt < 2; mt++)
                #pragma unroll
                for (int nt = 0; nt < 4; nt++)
                    mma_bf16(acc[mt][nt][0], acc[mt][nt][1], acc[mt][nt][2], acc[mt][nt][3],
                             F.ah[mt][0], F.ah[mt][1], F.ah[mt][2], F.ah[mt][3],
                             F.bh0[nt], F.bh1[nt]);
            #pragma unroll
            for (int mt = 0; mt < 2; mt++)
                #pragma unroll
                for (int nt = 0; nt < 2; nt++)
                    mma_bf16(acc[mt][nt][0], acc[mt][nt][1], acc[mt][nt][2], acc[mt][nt][3],
                             F.ah[mt][0], F.ah[mt][1], F.ah[mt][2], F.ah[mt][3],
                             F.bl0[nt], F.bl1[nt]);
            #pragma unroll
            for (int mt = 0; mt < 2; mt++)
                #pragma unroll
                for (int nt = 0; nt < 4; nt++)
                    mma_bf16(acc[mt][nt][0], acc[mt][nt][1], acc[mt][nt][2], acc[mt][nt][3],
                             F.al[mt][0], F.al[mt][1], F.al[mt][2], F.al[mt][3],
                             F.bh0[nt], F.bh1[nt]);
            if (ks < 3) F = Fn;
        }
        __syncthreads();
    }

    int r0 = m0 + warp_m + (lane >> 2);
    #pragma unroll
    for (int mt = 0; mt < 2; mt++) {
        #pragma unroll
        for (int nt = 0; nt < 4; nt++) {
            int cb = (nt >= 2 ? 512 : 0) + pn64 + w2 * 16 + (nt & 1) * 8 + (lane & 3) * 2;
            *(float2*)&g_U[(size_t)(r0 + mt * 16) * 1024 + cb] =
                make_float2(acc[mt][nt][0], acc[mt][nt][1]);
            *(float2*)&g_U[(size_t)(r0 + mt * 16 + 8) * 1024 + cb] =
                make_float2(acc[mt][nt][2], acc[mt][nt][3]);
        }
    }
}

// ---------------------------------------------------------------------------
// Kernel 4: pointwise epilogue, 8 elements/thread, 256 thr x 256 blocks
// (doubles warps/SM vs round 10 while keeping 2x coeff amortization)
// ---------------------------------------------------------------------------
__global__ __launch_bounds__(256) void epilogue_kernel(
    const float* __restrict__ x, const int* __restrict__ mask,
    const float* __restrict__ bfs, float* __restrict__ out) {
    __shared__ float s_scd[512];
    __shared__ float s_c12[256];
    __shared__ float s_r56[128];
    __shared__ float s_mt[65], s_msa[65], s_msb[65];
    int tid = threadIdx.x;
    for (int i = tid; i < 512; i += 256) s_scd[i] = g_scd[i];
    s_c12[tid] = g_c12[tid];
    if (tid < 128) s_r56[tid] = g_r56[tid];
    if (tid < 65) { s_mt[tid] = g_mt[tid]; s_msa[tid] = g_msa[tid]; s_msb[tid] = g_msb[tid]; }
    __syncthreads();
    float bfs0 = bfs[0];

    int gid = blockIdx.x * 256 + tid;   // 0..65535
    int e = gid * 8;
    int b = e >> 16;
    int rem = e & 65535;
    int j = rem >> 6;
    int tt = rem & 63;
    int c = b * 64 + tt;
    size_t ubase = (size_t)j * 1024 + c;
    float sj = g_S[j];

    unsigned long long x1p[4], mfp[4], u1p[4], u2p[4];
    #pragma unroll
    for (int g = 0; g < 2; g++) {
        float4 xv = *(const float4*)&x[e + g * 4];
        int4 mv = *(const int4*)&mask[e + g * 4];
        float4 u1v = *(const float4*)&g_U[ubase + g * 4];
        float4 u2v = *(const float4*)&g_U[ubase + 512 + g * 4];
        float a0 = mv.x ? xv.x : bfs0;
        float a1 = mv.y ? xv.y : bfs0;
        float a2 = mv.z ? xv.z : bfs0;
        float a3 = mv.w ? xv.w : bfs0;
        x1p[g * 2]     = pack2(a0, a1);
        x1p[g * 2 + 1] = pack2(a2, a3);
        mfp[g * 2]     = pack2((float)mv.x, (float)mv.y);
        mfp[g * 2 + 1] = pack2((float)mv.z, (float)mv.w);
        u1p[g * 2]     = pack2(u1v.x, u1v.y);
        u1p[g * 2 + 1] = pack2(u1v.z, u1v.w);
        u2p[g * 2]     = pack2(u2v.x, u2v.y);
        u2p[g * 2 + 1] = pack2(u2v.z, u2v.w);
    }

    unsigned long long acc2[4];
    #pragma unroll
    for (int q = 0; q < 4; q++) acc2[q] = 0ULL;

    #pragma unroll 4
    for (int h = 0; h < 64; h++) {
        ulonglong2 r12 = *(const ulonglong2*)&s_scd[h * 8];
        ulonglong2 r34 = *(const ulonglong2*)&s_scd[h * 8 + 4];
        float2 r56v = *(const float2*)&s_r56[h * 2];
        ulonglong2 cc = *(const ulonglong2*)&s_c12[h * 4];
        float base = fmaf(r56v.x, sj, r56v.y);
        unsigned long long base2 = pack2(base, base);
        #pragma unroll
        for (int q = 0; q < 4; q++) {
            unsigned long long v =
                ffma2(r12.x, x1p[q],
                ffma2(r12.y, mfp[q],
                ffma2(r34.x, u1p[q],
                ffma2(r34.y, u2p[q], base2))));
            unsigned long long av = v & 0x7fffffff7fffffffULL;
            acc2[q] = ffma2(cc.x, v, acc2[q]);
            acc2[q] = ffma2(cc.y, av, acc2[q]);
        }
    }

    #pragma unroll
    for (int g = 0; g < 2; g++) {
        float accs[4];
        { U64 p; p.u = acc2[g * 2];     accs[0] = p.f.x; accs[1] = p.f.y; }
        { U64 p; p.u = acc2[g * 2 + 1]; accs[2] = p.f.x; accs[3] = p.f.y; }
        float res[4];
        #pragma unroll
        for (int q = 0; q < 4; q++) {
            float xs = accs[q];
            int k = 0;
            #pragma unroll
            for (int step = 64; step > 0; step >>= 1) {
                if (k + step <= 64 && s_mt[k + step] <= xs) k += step;
            }
            res[q] = fmaf(s_msa[k], xs, s_msb[k]);
        }
        *(float4*)&out[e + g * 4] = make_float4(res[0], res[1], res[2], res[3]);
    }
}

// ---------------------------------------------------------------------------
// Launch
// ---------------------------------------------------------------------------
extern "C" void kernel_launch(void* const* d_in, const int* in_sizes, int n_in,
                              void* d_out, int out_size) {
    const float* x      = (const float*)d_in[0];
    const int*   mask   = (const int*)  d_in[1];
    const float* b_fs   = (const float*)d_in[3];
    const float* W_in   = (const float*)d_in[4];
    const float* b_in   = (const float*)d_in[5];
    const float* adj    = (const float*)d_in[6];
    const float* W_gc   = (const float*)d_in[7];
    const float* b_gc   = (const float*)d_in[8];
    const float* W_lo   = (const float*)d_in[9];
    const float* b_lo   = (const float*)d_in[10];
    const float* prelua = (const float*)d_in[11];
    const float* W_ro   = (const float*)d_in[12];
    const float* b_ro   = (const float*)d_in[13];
    const float* W_o1   = (const float*)d_in[14];
    const float* b_o1   = (const float*)d_in[15];
    const float* W_o2   = (const float*)d_in[16];
    const float* b_o2   = (const float*)d_in[17];
    float* out = (float*)d_out;

    cudaFuncSetAttribute(mma_kernel, cudaFuncAttributeMaxDynamicSharedMemorySize, MMA_SMEM);

    coef_kernel<<<1, 64>>>(W_in, b_in, W_gc, b_gc, W_lo, b_lo, W_ro, prelua,
                           W_o1, b_o1, W_o2, b_o2, b_ro);
    prep_kernel<<<1280, 256>>>(adj, x, mask, b_fs);
    mma_kernel<<<128, 256, MMA_SMEM>>>();
    epilogue_kernel<<<256, 256>>>(x, mask, b_fs, out);
}